// round 2
// baseline (speedup 1.0000x reference)
#include <cuda_runtime.h>
#include <math.h>

#define BB 64
#define TT 256
#define EE 300
#define HH 256
#define G4H 1024
#define NINTER 128
#define NL 17
#define TL 19
#define START_IDX 17
#define END_IDX 18
#define LOW_POT -10000.0f

// ---------------- device scratch (static; no allocations allowed) ----------------
__device__ float g_xp[2][TT][G4H][BB];        // 128 MB: x_proj, [dir][t][gate_row][b]
__device__ float g_h[2][2][HH][BB];           // h state double-buffered, transposed [k][b]
__device__ float g_hs[TT][BB][2 * HH];        // hidden history for fc1: rows m=t*64+b, K=512
__device__ float g_unary[BB][TT][NL];         // classifier outputs
__device__ unsigned int g_bar_count;
__device__ volatile unsigned int g_bar_gen;

// ---------------- software grid barrier (128 co-resident blocks) ----------------
__device__ __forceinline__ void grid_barrier(unsigned nb)
{
    __syncthreads();
    if (threadIdx.x == 0) {
        unsigned g = g_bar_gen;
        __threadfence();
        unsigned t = atomicAdd(&g_bar_count, 1u);
        if (t == nb - 1u) {
            g_bar_count = 0u;
            __threadfence();
            g_bar_gen = g + 1u;
        } else {
            while (g_bar_gen == g) { }
        }
        __threadfence();
    }
    __syncthreads();
}

// =======================================================================
// Kernel A: embedding gather + x_proj GEMM (both directions)
// out[dir][t][g][b] = sum_k emb[x[b,t]][k] * W_ih[dir][g][k] + bias[dir][g]
// grid: (T, 32) blocks of 256 threads; each block: 64 gate-rows x 64 batches
// =======================================================================
__global__ void xproj_kernel(const int* __restrict__ x,
                             const float* __restrict__ emb,
                             const float* __restrict__ Wf,
                             const float* __restrict__ bf,
                             const float* __restrict__ Wb,
                             const float* __restrict__ bb)
{
    int t = blockIdx.x;
    int gt = blockIdx.y;            // 0..31
    int dir = gt >> 4;
    int grow0 = (gt & 15) * 64;
    const float* W = dir ? Wb : Wf;
    const float* bias = dir ? bb : bf;

    __shared__ float sW[20][64];
    __shared__ float sE[20][64];
    __shared__ int sTok[64];

    int tid = threadIdx.x;
    if (tid < 64) sTok[tid] = x[tid * TT + t];
    __syncthreads();

    int tg = tid & 15, tb = tid >> 4;
    int g0 = tg * 4, b0 = tb * 4;

    float acc[4][4];
#pragma unroll
    for (int i = 0; i < 4; i++)
#pragma unroll
        for (int j = 0; j < 4; j++) acc[i][j] = 0.f;

    for (int kc = 0; kc < EE; kc += 20) {
        __syncthreads();
        for (int idx = tid; idx < 1280; idx += 256) {
            int g = idx / 20, k = idx % 20;
            sW[k][g] = W[(grow0 + g) * EE + kc + k];
        }
        for (int idx = tid; idx < 1280; idx += 256) {
            int b = idx / 20, k = idx % 20;
            sE[k][b] = emb[(long)sTok[b] * EE + kc + k];
        }
        __syncthreads();
#pragma unroll
        for (int k = 0; k < 20; k++) {
            float4 w4 = *(const float4*)&sW[k][g0];
            float4 e4 = *(const float4*)&sE[k][b0];
            float wv[4] = {w4.x, w4.y, w4.z, w4.w};
            float ev[4] = {e4.x, e4.y, e4.z, e4.w};
#pragma unroll
            for (int i = 0; i < 4; i++)
#pragma unroll
                for (int j = 0; j < 4; j++) acc[i][j] += wv[i] * ev[j];
        }
    }

#pragma unroll
    for (int i = 0; i < 4; i++) {
        int g = grow0 + g0 + i;
        float bv = bias[g];
        float4 o = make_float4(acc[i][0] + bv, acc[i][1] + bv,
                               acc[i][2] + bv, acc[i][3] + bv);
        *(float4*)&g_xp[dir][t][g][b0] = o;
    }
}

// =======================================================================
// Kernel B: persistent BiLSTM. 128 blocks (64/dir) x 256 threads.
// Block owns 4 h-cols: 16 W_hh rows resident in smem; per step loads h_old
// [256][64] into smem, computes its 16x64 gate tile, nonlinearity, writes
// h_new + history, grid barrier.
// =======================================================================
__global__ void lstm_kernel(const float* __restrict__ Whf,
                            const float* __restrict__ Whb)
{
    extern __shared__ float sm[];
    float* sW = sm;                     // 16 x 257
    float* sH = sm + 16 * 257;          // 256 x 64
    float* sG = sH + 256 * 64;          // 16 x 68

    int tid = threadIdx.x;
    int bid = blockIdx.x;               // 0..127
    int dir = bid & 1;
    int grp = bid >> 1;                 // 0..63
    int c0 = grp * 4;
    const float* Whh = dir ? Whb : Whf;

    // load 16 W_hh rows (rows {gate*256 + c0 + ci}) with row stride 257 (bank-safe)
    for (int idx = tid; idx < 4096; idx += 256) {
        int r = idx >> 8, k = idx & 255;
        int gate = r >> 2, ci = r & 3;
        sW[r * 257 + k] = Whh[(gate * 256 + c0 + ci) * 256 + k];
    }
    // zero-init own slice of h buffer 0 (deterministic per replay)
    {
        int k = c0 + (tid >> 6);
        int b = tid & 63;
        g_h[dir][0][k][b] = 0.f;
    }
    float c_state = 0.f;

    int r = tid & 15, q = tid >> 4;     // phase-1 mapping: row r of 16, batch quad q
    int gate = r >> 2, ci_r = r & 3;
    int wrow = gate * 256 + c0 + ci_r;
    int ci2 = tid >> 6, b2 = tid & 63;  // phase-2 mapping: (col ci2, batch b2)

    grid_barrier(128u);

    int cur = 0;
    for (int s = 0; s < TT; s++) {
        int t = dir ? (TT - 1 - s) : s;

        // load h_old (transposed [k][b]) into smem, 16 float4 per thread, coalesced
        const float4* hsrc = (const float4*)&g_h[dir][cur][0][0];
        float4* hdst = (float4*)sH;
#pragma unroll
        for (int i = 0; i < 16; i++) hdst[i * 256 + tid] = hsrc[i * 256 + tid];
        __syncthreads();

        // phase 1: 16x64x256 GEMM tile; acc initialized from x_proj
        float4 a = *(const float4*)&g_xp[dir][t][wrow][q * 4];
        float acc0 = a.x, acc1 = a.y, acc2 = a.z, acc3 = a.w;
        const float* wrowp = &sW[r * 257];
        const float4* hq = (const float4*)sH + q;
#pragma unroll 8
        for (int k = 0; k < 256; k++) {
            float w = wrowp[k];
            float4 h4 = hq[k * 16];
            acc0 += w * h4.x; acc1 += w * h4.y;
            acc2 += w * h4.z; acc3 += w * h4.w;
        }
        *(float4*)&sG[r * 68 + q * 4] = make_float4(acc0, acc1, acc2, acc3);
        __syncthreads();

        // phase 2: gate nonlinearity + state update for (col c0+ci2, batch b2)
        float gi = sG[(0 + ci2) * 68 + b2];
        float gf = sG[(4 + ci2) * 68 + b2];
        float gg = sG[(8 + ci2) * 68 + b2];
        float go = sG[(12 + ci2) * 68 + b2];
        float i_s = 1.f / (1.f + __expf(-gi));
        float f_s = 1.f / (1.f + __expf(-gf));
        float o_s = 1.f / (1.f + __expf(-go));
        float c_new = f_s * c_state + i_s * tanhf(gg);
        c_state = c_new;
        float h_new = o_s * tanhf(c_new);

        g_h[dir][cur ^ 1][c0 + ci2][b2] = h_new;            // coalesced
        g_hs[t][b2][dir * 256 + c0 + ci2] = h_new;          // history for fc1
        cur ^= 1;

        grid_barrier(128u);
    }
}

// =======================================================================
// Kernel C: fc1 + ReLU + classifier -> unary. 256 blocks x 256 threads.
// Block handles 64 rows (m = t*64+b). Stage 1: [64x128x512] GEMM into smem;
// Stage 2: [64x17x128] GEMM -> g_unary.
// =======================================================================
__global__ void fc_kernel(const float* __restrict__ fc1W,
                          const float* __restrict__ fc1b,
                          const float* __restrict__ clsW,
                          const float* __restrict__ clsb)
{
    extern __shared__ float sm[];
    float* sA = sm;                  // 32 x 64
    float* sB = sm + 2048;           // 32 x 128
    float* sI = sm + 6144;           // 64 x 128

    int tid = threadIdx.x;
    int m0 = blockIdx.x * 64;
    const float* hs = &g_hs[0][0][0];

    int tr = tid >> 4, tn = tid & 15;
    int r0 = tr * 4, n0 = tn * 8;

    float acc[4][8];
#pragma unroll
    for (int i = 0; i < 4; i++)
#pragma unroll
        for (int j = 0; j < 8; j++) acc[i][j] = 0.f;

    for (int kc = 0; kc < 512; kc += 32) {
        __syncthreads();
        for (int idx = tid; idx < 512; idx += 256) {       // hs tile, transpose to [k][m]
            int m = idx >> 3, kq = idx & 7;
            float4 v = *(const float4*)&hs[(m0 + m) * 512 + kc + kq * 4];
            sA[(kq * 4 + 0) * 64 + m] = v.x;
            sA[(kq * 4 + 1) * 64 + m] = v.y;
            sA[(kq * 4 + 2) * 64 + m] = v.z;
            sA[(kq * 4 + 3) * 64 + m] = v.w;
        }
        for (int idx = tid; idx < 1024; idx += 256) {      // fc1_W tile -> [k][n]
            int n = idx >> 3, kq = idx & 7;
            float4 v = *(const float4*)&fc1W[n * 512 + kc + kq * 4];
            sB[(kq * 4 + 0) * 128 + n] = v.x;
            sB[(kq * 4 + 1) * 128 + n] = v.y;
            sB[(kq * 4 + 2) * 128 + n] = v.z;
            sB[(kq * 4 + 3) * 128 + n] = v.w;
        }
        __syncthreads();
#pragma unroll
        for (int k = 0; k < 32; k++) {
            float4 a4 = *(const float4*)&sA[k * 64 + r0];
            float4 bA = *(const float4*)&sB[k * 128 + n0];
            float4 bBv = *(const float4*)&sB[k * 128 + n0 + 4];
            float av[4] = {a4.x, a4.y, a4.z, a4.w};
            float bv[8] = {bA.x, bA.y, bA.z, bA.w, bBv.x, bBv.y, bBv.z, bBv.w};
#pragma unroll
            for (int i = 0; i < 4; i++)
#pragma unroll
                for (int j = 0; j < 8; j++) acc[i][j] += av[i] * bv[j];
        }
    }

    // bias + relu -> sI
#pragma unroll
    for (int i = 0; i < 4; i++)
#pragma unroll
        for (int j = 0; j < 8; j++) {
            float v = acc[i][j] + fc1b[n0 + j];
            sI[(r0 + i) * 128 + n0 + j] = fmaxf(v, 0.f);
        }
    __syncthreads();

    // stage 2: classifier. cls_W staged with stride 129 (bank-safe)
    float* sCW = sA;   // reuse sA+sB region (17*129 = 2193 floats < 6144)
    for (int idx = tid; idx < NL * 128; idx += 256) {
        int l = idx >> 7, k = idx & 127;
        sCW[l * 129 + k] = clsW[idx];
    }
    __syncthreads();

    for (int oi = tid; oi < 64 * NL; oi += 256) {
        int rr = oi / NL, l = oi % NL;
        const float* ip = &sI[rr * 128];
        const float* wp = &sCW[l * 129];
        float s = 0.f;
#pragma unroll 8
        for (int k = 0; k < 128; k++) s += ip[k] * wp[k];
        s += clsb[l];
        int m = m0 + rr;
        int b = m & 63, t = m >> 6;
        g_unary[b][t][l] = s;
    }
}

// =======================================================================
// Kernel D: Viterbi decode. 64 blocks (1 per batch) x 32 threads.
// =======================================================================
__global__ void viterbi_kernel(const float* __restrict__ trans,
                               float* __restrict__ out)
{
    __shared__ float tpn[TL * TL];          // tpn[prev][next] = trans[next][prev]
    __shared__ float score[TL];
    __shared__ float fin[TL];
    __shared__ unsigned char bp[TT][TL];

    int b = blockIdx.x;
    int lane = threadIdx.x;

    for (int i = lane; i < TL * TL; i += 32) {
        int p = i / TL, n = i % TL;
        tpn[i] = trans[n * TL + p];
    }
    if (lane < TL) score[lane] = (lane == START_IDX) ? 0.f : LOW_POT;
    __syncwarp();

    for (int t = 0; t < TT; t++) {
        float best = -3.4e38f;
        int bestp = 0;
        if (lane < TL) {
            const float* tp = &tpn[lane];
#pragma unroll
            for (int p = 0; p < TL; p++) {
                float v = score[p] + tp[p * TL];
                if (v > best) { best = v; bestp = p; }
            }
            float u = (lane < NL) ? g_unary[b][t][lane] : LOW_POT;
            bp[t][lane] = (unsigned char)bestp;
            best += u;
        }
        __syncwarp();
        if (lane < TL) score[lane] = best;
        __syncwarp();
    }

    if (lane < TL) fin[lane] = score[lane] + trans[END_IDX * TL + lane];
    __syncwarp();

    if (lane == 0) {
        float best = -3.4e38f;
        int bl = 0;
        for (int l = 0; l < TL; l++)
            if (fin[l] > best) { best = fin[l]; bl = l; }
        out[b] = best;
        int cur = bl;
        for (int t = TT - 1; t >= 0; t--) {
            out[BB + b * TT + t] = (float)cur;
            cur = bp[t][cur];
        }
    }
}

// =======================================================================
extern "C" void kernel_launch(void* const* d_in, const int* in_sizes, int n_in,
                              void* d_out, int out_size)
{
    const int*   x     = (const int*)d_in[0];
    const float* emb   = (const float*)d_in[1];
    const float* Wif   = (const float*)d_in[2];
    const float* Whf   = (const float*)d_in[3];
    const float* bf    = (const float*)d_in[4];
    const float* Wib   = (const float*)d_in[5];
    const float* Whb   = (const float*)d_in[6];
    const float* bb    = (const float*)d_in[7];
    const float* fc1W  = (const float*)d_in[8];
    const float* fc1b  = (const float*)d_in[9];
    const float* clsW  = (const float*)d_in[10];
    const float* clsb  = (const float*)d_in[11];
    const float* trans = (const float*)d_in[12];
    float* out = (float*)d_out;

    size_t smemB = (16 * 257 + 256 * 64 + 16 * 68) * sizeof(float);   // 86336 B
    size_t smemC = (2048 + 4096 + 64 * 128) * sizeof(float);          // 57344 B
    cudaFuncSetAttribute(lstm_kernel, cudaFuncAttributeMaxDynamicSharedMemorySize, (int)smemB);
    cudaFuncSetAttribute(fc_kernel,   cudaFuncAttributeMaxDynamicSharedMemorySize, (int)smemC);

    dim3 gridA(TT, 32);
    xproj_kernel<<<gridA, 256>>>(x, emb, Wif, bf, Wib, bb);
    lstm_kernel<<<128, 256, smemB>>>(Whf, Whb);
    fc_kernel<<<TT * BB / 64, 256, smemC>>>(fc1W, fc1b, clsW, clsb);
    viterbi_kernel<<<BB, 32>>>(trans, out);
}

// round 3
// speedup vs baseline: 1.0687x; 1.0687x over previous
#include <cuda_runtime.h>
#include <math.h>

#define BB 64
#define TT 256
#define EE 300
#define HH 256
#define G4H 1024
#define NINTER 128
#define NL 17
#define TL 19
#define START_IDX 17
#define END_IDX 18
#define LOW_POT -10000.0f

// ---------------- device scratch (static; no allocations allowed) ----------------
__device__ float g_xp[2][TT][G4H][BB];        // 128 MB: x_proj, [dir][t][gate_row][b]
__device__ float g_h[2][2][HH][BB];           // h state double-buffered, transposed [k][b]
__device__ float g_hs[TT][2 * HH][BB];        // hidden history, [t][k][b] (coalesced both ways)
__device__ float g_unary[BB][TT][NL];         // classifier outputs
__device__ unsigned int g_bar_count;
__device__ volatile unsigned int g_bar_gen;
__device__ volatile unsigned int g_flag[128][8];   // padded: one 32B sector per block

// ---------------- atomic grid barrier (used once at end for flag reset) ---------
__device__ __forceinline__ void grid_barrier(unsigned nb)
{
    __syncthreads();
    if (threadIdx.x == 0) {
        unsigned g = g_bar_gen;
        __threadfence();
        unsigned t = atomicAdd(&g_bar_count, 1u);
        if (t == nb - 1u) {
            g_bar_count = 0u;
            __threadfence();
            g_bar_gen = g + 1u;
        } else {
            while (g_bar_gen == g) { }
        }
        __threadfence();
    }
    __syncthreads();
}

// ---------------- cp.async helpers ----------------
__device__ __forceinline__ void cp_async16(unsigned smem_addr, const void* gptr)
{
    asm volatile("cp.async.cg.shared.global [%0], [%1], 16;\n"
                 :: "r"(smem_addr), "l"(gptr));
}
__device__ __forceinline__ void cp_commit()
{
    asm volatile("cp.async.commit_group;\n");
}
template <int N>
__device__ __forceinline__ void cp_wait()
{
    asm volatile("cp.async.wait_group %0;\n" :: "n"(N));
}

// =======================================================================
// Kernel A: embedding gather + x_proj GEMM (both directions)
// out[dir][t][g][b] = sum_k emb[x[b,t]][k] * W_ih[dir][g][k] + bias[dir][g]
// grid: (T, 32) blocks of 256 threads; each block: 64 gate-rows x 64 batches
// =======================================================================
__global__ void xproj_kernel(const int* __restrict__ x,
                             const float* __restrict__ emb,
                             const float* __restrict__ Wf,
                             const float* __restrict__ bf,
                             const float* __restrict__ Wb,
                             const float* __restrict__ bb)
{
    int t = blockIdx.x;
    int gt = blockIdx.y;            // 0..31
    int dir = gt >> 4;
    int grow0 = (gt & 15) * 64;
    const float* W = dir ? Wb : Wf;
    const float* bias = dir ? bb : bf;

    __shared__ float sW[20][64];
    __shared__ float sE[20][64];
    __shared__ int sTok[64];

    int tid = threadIdx.x;
    if (tid < 64) sTok[tid] = x[tid * TT + t];
    __syncthreads();

    int tg = tid & 15, tb = tid >> 4;
    int g0 = tg * 4, b0 = tb * 4;

    float acc[4][4];
#pragma unroll
    for (int i = 0; i < 4; i++)
#pragma unroll
        for (int j = 0; j < 4; j++) acc[i][j] = 0.f;

    for (int kc = 0; kc < EE; kc += 20) {
        __syncthreads();
        for (int idx = tid; idx < 1280; idx += 256) {
            int g = idx / 20, k = idx % 20;
            sW[k][g] = W[(grow0 + g) * EE + kc + k];
        }
        for (int idx = tid; idx < 1280; idx += 256) {
            int b = idx / 20, k = idx % 20;
            sE[k][b] = emb[(long)sTok[b] * EE + kc + k];
        }
        __syncthreads();
#pragma unroll
        for (int k = 0; k < 20; k++) {
            float4 w4 = *(const float4*)&sW[k][g0];
            float4 e4 = *(const float4*)&sE[k][b0];
            float wv[4] = {w4.x, w4.y, w4.z, w4.w};
            float ev[4] = {e4.x, e4.y, e4.z, e4.w};
#pragma unroll
            for (int i = 0; i < 4; i++)
#pragma unroll
                for (int j = 0; j < 4; j++) acc[i][j] += wv[i] * ev[j];
        }
    }

#pragma unroll
    for (int i = 0; i < 4; i++) {
        int g = grow0 + g0 + i;
        float bv = bias[g];
        float4 o = make_float4(acc[i][0] + bv, acc[i][1] + bv,
                               acc[i][2] + bv, acc[i][3] + bv);
        *(float4*)&g_xp[dir][t][g][b0] = o;
    }
}

// =======================================================================
// Kernel B: persistent BiLSTM. 128 blocks (64/dir) x 256 threads.
// Flag-array step barrier (distributed, no atomics), cp.async pipelined
// h broadcast, x_proj prefetch.
// =======================================================================
__global__ void __launch_bounds__(256, 1)
lstm_kernel(const float* __restrict__ Whf,
            const float* __restrict__ Whb)
{
    extern __shared__ float sm[];
    float* sW = sm;                     // 16 x 257
    float* sH = sm + 16 * 257;          // 256 x 64
    float* sG = sH + 256 * 64;          // 16 x 68

    int tid = threadIdx.x;
    int bid = blockIdx.x;               // 0..127
    int dir = bid & 1;
    int grp = bid >> 1;                 // 0..63
    int c0 = grp * 4;
    const float* Whh = dir ? Whb : Whf;

    // load 16 W_hh rows (rows {gate*256 + c0 + ci}) with row stride 257 (bank-safe)
    for (int idx = tid; idx < 4096; idx += 256) {
        int r = idx >> 8, k = idx & 255;
        int gate = r >> 2, ci = r & 3;
        sW[r * 257 + k] = Whh[(gate * 256 + c0 + ci) * 256 + k];
    }
    // zero-init own slice of h buffer 0
    g_h[dir][0][c0 + (tid >> 6)][tid & 63] = 0.f;
    float c_state = 0.f;

    int r = tid & 15, q = tid >> 4;     // phase-1 mapping: row r of 16, batch quad q
    int wrow = (r >> 2) * 256 + c0 + (r & 3);
    int ci2 = tid >> 6, b2 = tid & 63;  // phase-2 mapping: (col ci2, batch b2)

    unsigned sH_addr = (unsigned)__cvta_generic_to_shared(sH);
    const float* wrowp = &sW[r * 257];
    const float4* hq = (const float4*)sH + q;

    __syncthreads();
    if (tid == 0) { __threadfence(); g_flag[bid][0] = 1u; }

    for (int s = 0; s < TT; s++) {
        int t = dir ? (TT - 1 - s) : s;

        // prefetch x_proj tile (independent of flags)
        float4 a = __ldg((const float4*)&g_xp[dir][t][wrow][0] + q);

        // wait: all 128 blocks have published h generation s
        if (tid < 128) {
            unsigned tgt = (unsigned)(s + 1);
            while (g_flag[tid][0] < tgt) { }
            __threadfence();
        }
        __syncthreads();

        // pipelined h broadcast: two 32KB halves via cp.async
        const float4* hsrc = (const float4*)&g_h[dir][s & 1][0][0];
#pragma unroll
        for (int i = 0; i < 8; i++)
            cp_async16(sH_addr + (unsigned)((i * 256 + tid) * 16), hsrc + i * 256 + tid);
        cp_commit();
#pragma unroll
        for (int i = 8; i < 16; i++)
            cp_async16(sH_addr + (unsigned)((i * 256 + tid) * 16), hsrc + i * 256 + tid);
        cp_commit();

        float acc0 = a.x, acc1 = a.y, acc2 = a.z, acc3 = a.w;

        cp_wait<1>();
        __syncthreads();
#pragma unroll 8
        for (int k = 0; k < 128; k++) {
            float w = wrowp[k];
            float4 h4 = hq[k * 16];
            acc0 += w * h4.x; acc1 += w * h4.y;
            acc2 += w * h4.z; acc3 += w * h4.w;
        }
        cp_wait<0>();
        __syncthreads();
#pragma unroll 8
        for (int k = 128; k < 256; k++) {
            float w = wrowp[k];
            float4 h4 = hq[k * 16];
            acc0 += w * h4.x; acc1 += w * h4.y;
            acc2 += w * h4.z; acc3 += w * h4.w;
        }
        *(float4*)&sG[r * 68 + q * 4] = make_float4(acc0, acc1, acc2, acc3);
        __syncthreads();

        // phase 2: gate nonlinearity + state update for (col c0+ci2, batch b2)
        float gi = sG[(0 + ci2) * 68 + b2];
        float gf = sG[(4 + ci2) * 68 + b2];
        float gg = sG[(8 + ci2) * 68 + b2];
        float go = sG[(12 + ci2) * 68 + b2];
        float i_s = 1.f / (1.f + __expf(-gi));
        float f_s = 1.f / (1.f + __expf(-gf));
        float o_s = 1.f / (1.f + __expf(-go));
        float c_new = f_s * c_state + i_s * tanhf(gg);
        c_state = c_new;
        float h_new = o_s * tanhf(c_new);

        g_h[dir][(s + 1) & 1][c0 + ci2][b2] = h_new;        // coalesced
        g_hs[t][dir * 256 + c0 + ci2][b2] = h_new;          // coalesced ([t][k][b])

        __syncthreads();
        if (tid == 0) { __threadfence(); g_flag[bid][0] = (unsigned)(s + 2); }
    }

    // all blocks past every poll, then reset flags for the next graph replay
    grid_barrier(128u);
    if (tid == 0) g_flag[bid][0] = 0u;
}

// =======================================================================
// Kernel C: fc1 + ReLU + classifier -> unary. 256 blocks (one t each).
// =======================================================================
__global__ void fc_kernel(const float* __restrict__ fc1W,
                          const float* __restrict__ fc1b,
                          const float* __restrict__ clsW,
                          const float* __restrict__ clsb)
{
    extern __shared__ float sm[];
    float* sA = sm;                  // 32 x 64
    float* sB = sm + 2048;           // 32 x 128
    float* sI = sm + 6144;           // 64 x 128

    int tid = threadIdx.x;
    int t = blockIdx.x;

    int tr = tid >> 4, tn = tid & 15;
    int r0 = tr * 4, n0 = tn * 8;

    float acc[4][8];
#pragma unroll
    for (int i = 0; i < 4; i++)
#pragma unroll
        for (int j = 0; j < 8; j++) acc[i][j] = 0.f;

    for (int kc = 0; kc < 512; kc += 32) {
        __syncthreads();
        for (int idx = tid; idx < 512; idx += 256) {       // hs tile [k][b], direct copy
            int k = idx >> 4, b4 = idx & 15;
            *(float4*)&sA[k * 64 + b4 * 4] =
                *(const float4*)&g_hs[t][kc + k][b4 * 4];
        }
        for (int idx = tid; idx < 1024; idx += 256) {      // fc1_W tile -> [k][n]
            int n = idx >> 3, kq = idx & 7;
            float4 v = *(const float4*)&fc1W[n * 512 + kc + kq * 4];
            sB[(kq * 4 + 0) * 128 + n] = v.x;
            sB[(kq * 4 + 1) * 128 + n] = v.y;
            sB[(kq * 4 + 2) * 128 + n] = v.z;
            sB[(kq * 4 + 3) * 128 + n] = v.w;
        }
        __syncthreads();
#pragma unroll
        for (int k = 0; k < 32; k++) {
            float4 a4 = *(const float4*)&sA[k * 64 + r0];
            float4 bA = *(const float4*)&sB[k * 128 + n0];
            float4 bBv = *(const float4*)&sB[k * 128 + n0 + 4];
            float av[4] = {a4.x, a4.y, a4.z, a4.w};
            float bv[8] = {bA.x, bA.y, bA.z, bA.w, bBv.x, bBv.y, bBv.z, bBv.w};
#pragma unroll
            for (int i = 0; i < 4; i++)
#pragma unroll
                for (int j = 0; j < 8; j++) acc[i][j] += av[i] * bv[j];
        }
    }

    // bias + relu -> sI
#pragma unroll
    for (int i = 0; i < 4; i++)
#pragma unroll
        for (int j = 0; j < 8; j++) {
            float v = acc[i][j] + fc1b[n0 + j];
            sI[(r0 + i) * 128 + n0 + j] = fmaxf(v, 0.f);
        }
    __syncthreads();

    // stage 2: classifier. cls_W staged with stride 129 (bank-safe)
    float* sCW = sA;   // reuse sA+sB region (17*129 floats < 6144)
    for (int idx = tid; idx < NL * 128; idx += 256) {
        int l = idx >> 7, k = idx & 127;
        sCW[l * 129 + k] = clsW[idx];
    }
    __syncthreads();

    for (int oi = tid; oi < 64 * NL; oi += 256) {
        int b = oi / NL, l = oi % NL;
        const float* ip = &sI[b * 128];
        const float* wp = &sCW[l * 129];
        float s = 0.f;
#pragma unroll 8
        for (int k = 0; k < 128; k++) s += ip[k] * wp[k];
        g_unary[b][t][l] = s + clsb[l];
    }
}

// =======================================================================
// Kernel D: Viterbi decode. 16 blocks x 128 threads, 1 warp per batch.
// Score lives in registers (lane l = score of label l), all-to-all via shfl.
// =======================================================================
__global__ void viterbi_kernel(const float* __restrict__ trans,
                               float* __restrict__ out)
{
    __shared__ float tpn_s[TL][20];                  // [prev][next], padded
    __shared__ unsigned char bps[4][TT][20];

    int tid = threadIdx.x;
    int warp = tid >> 5, lane = tid & 31;
    int b = blockIdx.x * 4 + warp;

    for (int i = tid; i < TL * TL; i += 128) {
        int p = i / TL, n = i % TL;
        tpn_s[p][n] = trans[n * TL + p];
    }
    __syncthreads();

    float tp[TL];
#pragma unroll
    for (int p = 0; p < TL; p++)
        tp[p] = (lane < TL) ? tpn_s[p][lane] : LOW_POT;

    float score = (lane == START_IDX) ? 0.f : LOW_POT;

    float u = (lane < NL) ? __ldg(&g_unary[b][0][lane]) : LOW_POT;

    for (int t = 0; t < TT; t++) {
        float u_next = (t + 1 < TT && lane < NL) ? __ldg(&g_unary[b][t + 1][lane]) : LOW_POT;

        float v[TL];
#pragma unroll
        for (int p = 0; p < TL; p++)
            v[p] = __shfl_sync(0xffffffffu, score, p) + tp[p];

        // 4-way ILP argmax over 19 candidates
        float m0 = v[0], m1 = v[5], m2 = v[10], m3 = v[15];
        int i0 = 0, i1 = 5, i2 = 10, i3 = 15;
#pragma unroll
        for (int p = 1; p < 5; p++) {
            if (v[p] > m0)      { m0 = v[p];      i0 = p; }
            if (v[5 + p] > m1)  { m1 = v[5 + p];  i1 = 5 + p; }
            if (v[10 + p] > m2) { m2 = v[10 + p]; i2 = 10 + p; }
            if (p < 4 && v[15 + p] > m3) { m3 = v[15 + p]; i3 = 15 + p; }
        }
        if (m1 > m0) { m0 = m1; i0 = i1; }
        if (m3 > m2) { m2 = m3; i2 = i3; }
        if (m2 > m0) { m0 = m2; i0 = i2; }

        if (lane < TL) bps[warp][t][lane] = (unsigned char)i0;
        score = m0 + u;
        u = u_next;
    }

    // final scores + warp argmax (ties -> lowest index, matching jnp.argmax)
    float fin = (lane < TL) ? score + trans[END_IDX * TL + lane] : -3.4e38f;
    int idx = lane;
#pragma unroll
    for (int off = 16; off > 0; off >>= 1) {
        float of = __shfl_down_sync(0xffffffffu, fin, off);
        int   oi = __shfl_down_sync(0xffffffffu, idx, off);
        if (of > fin || (of == fin && oi < idx)) { fin = of; idx = oi; }
    }

    if (lane == 0) {
        out[b] = fin;
        int cur = idx;
        for (int t = TT - 1; t >= 0; t--) {
            out[BB + b * TT + t] = (float)cur;
            cur = bps[warp][t][cur];
        }
    }
}

// =======================================================================
extern "C" void kernel_launch(void* const* d_in, const int* in_sizes, int n_in,
                              void* d_out, int out_size)
{
    const int*   x     = (const int*)d_in[0];
    const float* emb   = (const float*)d_in[1];
    const float* Wif   = (const float*)d_in[2];
    const float* Whf   = (const float*)d_in[3];
    const float* bf    = (const float*)d_in[4];
    const float* Wib   = (const float*)d_in[5];
    const float* Whb   = (const float*)d_in[6];
    const float* bb    = (const float*)d_in[7];
    const float* fc1W  = (const float*)d_in[8];
    const float* fc1b  = (const float*)d_in[9];
    const float* clsW  = (const float*)d_in[10];
    const float* clsb  = (const float*)d_in[11];
    const float* trans = (const float*)d_in[12];
    float* out = (float*)d_out;

    size_t smemB = (16 * 257 + 256 * 64 + 16 * 68) * sizeof(float);   // 86336 B
    size_t smemC = (2048 + 4096 + 64 * 128) * sizeof(float);          // 57344 B
    cudaFuncSetAttribute(lstm_kernel, cudaFuncAttributeMaxDynamicSharedMemorySize, (int)smemB);
    cudaFuncSetAttribute(fc_kernel,   cudaFuncAttributeMaxDynamicSharedMemorySize, (int)smemC);

    dim3 gridA(TT, 32);
    xproj_kernel<<<gridA, 256>>>(x, emb, Wif, bf, Wib, bb);
    lstm_kernel<<<128, 256, smemB>>>(Whf, Whb);
    fc_kernel<<<TT, 256, smemC>>>(fc1W, fc1b, clsW, clsb);
    viterbi_kernel<<<BB / 4, 128>>>(trans, out);
}

// round 4
// speedup vs baseline: 1.1486x; 1.0748x over previous
#include <cuda_runtime.h>
#include <math.h>

#define BB 64
#define TT 256
#define EE 300
#define HH 256
#define G4H 1024
#define NINTER 128
#define NL 17
#define TL 19
#define START_IDX 17
#define END_IDX 18
#define LOW_POT -10000.0f

// ---------------- device scratch (static; no allocations allowed) ----------------
__device__ float g_xp[2][TT][G4H][BB];        // x_proj, [dir][t][gate_row][b]
__device__ float g_h[2][2][HH][BB];           // h state double-buffered, transposed [k][b]
__device__ float g_hs[TT][2 * HH][BB];        // hidden history, [t][k][b]
__device__ float g_unary[BB][TT][NL];         // classifier outputs
__device__ unsigned int g_bar_count;
__device__ volatile unsigned int g_bar_gen;
__device__ volatile unsigned int g_flag[128][8];   // padded: one 32B sector per block

// ---------------- atomic grid barrier (flag reset at end of lstm) ---------------
__device__ __forceinline__ void grid_barrier(unsigned nb)
{
    __syncthreads();
    if (threadIdx.x == 0) {
        unsigned g = g_bar_gen;
        __threadfence();
        unsigned t = atomicAdd(&g_bar_count, 1u);
        if (t == nb - 1u) {
            g_bar_count = 0u;
            __threadfence();
            g_bar_gen = g + 1u;
        } else {
            while (g_bar_gen == g) { }
        }
        __threadfence();
    }
    __syncthreads();
}

// ---------------- cp.async helpers ----------------
__device__ __forceinline__ void cp_async16(unsigned smem_addr, const void* gptr)
{
    asm volatile("cp.async.cg.shared.global [%0], [%1], 16;\n"
                 :: "r"(smem_addr), "l"(gptr));
}
__device__ __forceinline__ void cp_commit()
{
    asm volatile("cp.async.commit_group;\n");
}
template <int N>
__device__ __forceinline__ void cp_wait()
{
    asm volatile("cp.async.wait_group %0;\n" :: "n"(N));
}

// ---------------- tf32 helpers ----------------
__device__ __forceinline__ unsigned f2tf32(float f)
{
    unsigned u;
    asm("cvt.rna.tf32.f32 %0, %1;" : "=r"(u) : "f"(f));
    return u;
}
__device__ __forceinline__ void mma_tf32(float c[4], const unsigned a[4], const unsigned b[2])
{
    asm volatile("mma.sync.aligned.m16n8k8.row.col.f32.tf32.tf32.f32 "
                 "{%0,%1,%2,%3}, {%4,%5,%6,%7}, {%8,%9}, {%0,%1,%2,%3};"
                 : "+f"(c[0]), "+f"(c[1]), "+f"(c[2]), "+f"(c[3])
                 : "r"(a[0]), "r"(a[1]), "r"(a[2]), "r"(a[3]),
                   "r"(b[0]), "r"(b[1]));
}

// =======================================================================
// Kernel A: embedding gather + x_proj GEMM via 3xTF32 tensor cores.
// C[g][b] = sum_k W[g][k]*E[b][k] + bias[g], per block: 64 g-rows x 64 b.
// Split each fp32 into tf32 hi+lo; D += Ahi*Bhi + Ahi*Blo + Alo*Bhi.
// grid: (T, 32) blocks of 256 threads (8 warps: 4 m-tiles x 2 n-halves).
// =======================================================================
__global__ void xproj_kernel(const int* __restrict__ x,
                             const float* __restrict__ emb,
                             const float* __restrict__ Wf,
                             const float* __restrict__ bf,
                             const float* __restrict__ Wb,
                             const float* __restrict__ bb)
{
    __shared__ unsigned sAh[32][72], sAl[32][72];   // W chunk  [k][m]
    __shared__ unsigned sBh[32][72], sBl[32][72];   // E chunk  [k][n]
    __shared__ int sTok[64];

    int t = blockIdx.x;
    int gt = blockIdx.y;            // 0..31
    int dir = gt >> 4;
    int grow0 = (gt & 15) * 64;
    const float* W = dir ? Wb : Wf;
    const float* bias = dir ? bb : bf;

    int tid = threadIdx.x;
    int warp = tid >> 5, lane = tid & 31;
    int m0 = (warp & 3) * 16;       // gate-row tile
    int n0 = (warp >> 2) * 32;      // batch half

    if (tid < 64) sTok[tid] = x[tid * TT + t];
    __syncthreads();

    float acc[4][4];                // 4 n-subtiles x 4 C regs
#pragma unroll
    for (int j = 0; j < 4; j++)
#pragma unroll
        for (int c = 0; c < 4; c++) acc[j][c] = 0.f;

    // register prefetch buffers (one K-chunk of 32: 8 elems/thread each matrix)
    float rw[8], re[8];

    // mapping for chunk loads: idx = i*256+tid; m(n) = idx>>5, k = idx&31
#define LOAD_CHUNK(kc)                                                        \
    {                                                                         \
        _Pragma("unroll")                                                     \
        for (int i = 0; i < 8; i++) {                                         \
            int idx = i * 256 + tid;                                          \
            int mm = idx >> 5, kk = (kc) + (idx & 31);                        \
            rw[i] = (kk < EE) ? W[(grow0 + mm) * EE + kk] : 0.f;              \
            re[i] = (kk < EE) ? emb[(long)sTok[mm] * EE + kk] : 0.f;          \
        }                                                                     \
    }

    LOAD_CHUNK(0)

    for (int c = 0; c < 10; c++) {
        __syncthreads();            // previous mma consumption done
        // convert + store this chunk
#pragma unroll
        for (int i = 0; i < 8; i++) {
            int idx = i * 256 + tid;
            int mm = idx >> 5, k = idx & 31;
            float fw = rw[i];
            unsigned wh = f2tf32(fw);
            sAh[k][mm] = wh;
            sAl[k][mm] = f2tf32(fw - __uint_as_float(wh));
            float fe = re[i];
            unsigned eh = f2tf32(fe);
            sBh[k][mm] = eh;
            sBl[k][mm] = f2tf32(fe - __uint_as_float(eh));
        }
        __syncthreads();
        if (c + 1 < 10) LOAD_CHUNK((c + 1) * 32)   // LDG in flight during mma

        // 4 k8-tiles of this chunk
#pragma unroll
        for (int kt = 0; kt < 4; kt++) {
            int k0 = kt * 8;
            int ka = k0 + (lane & 3);
            int ra = m0 + (lane >> 2);
            unsigned ah[4], al[4];
            ah[0] = sAh[ka][ra];     al[0] = sAl[ka][ra];
            ah[1] = sAh[ka][ra + 8]; al[1] = sAl[ka][ra + 8];
            ah[2] = sAh[ka + 4][ra];     al[2] = sAl[ka + 4][ra];
            ah[3] = sAh[ka + 4][ra + 8]; al[3] = sAl[ka + 4][ra + 8];
#pragma unroll
            for (int j = 0; j < 4; j++) {
                int nb = n0 + j * 8 + (lane >> 2);
                unsigned bh[2], bl[2];
                bh[0] = sBh[ka][nb];     bl[0] = sBl[ka][nb];
                bh[1] = sBh[ka + 4][nb]; bl[1] = sBl[ka + 4][nb];
                mma_tf32(acc[j], ah, bh);
                mma_tf32(acc[j], ah, bl);
                mma_tf32(acc[j], al, bh);
            }
        }
    }
#undef LOAD_CHUNK

    // epilogue: add bias, store to g_xp[dir][t][g][b]
    int row = m0 + (lane >> 2);
    int colb = (lane & 3) * 2;
    float bv0 = bias[grow0 + row];
    float bv8 = bias[grow0 + row + 8];
#pragma unroll
    for (int j = 0; j < 4; j++) {
        int col = n0 + j * 8 + colb;
        *(float2*)&g_xp[dir][t][grow0 + row][col] =
            make_float2(acc[j][0] + bv0, acc[j][1] + bv0);
        *(float2*)&g_xp[dir][t][grow0 + row + 8][col] =
            make_float2(acc[j][2] + bv8, acc[j][3] + bv8);
    }
}

// =======================================================================
// Kernel B: persistent BiLSTM. 128 blocks (64/dir) x 256 threads.
// =======================================================================
__global__ void __launch_bounds__(256, 1)
lstm_kernel(const float* __restrict__ Whf,
            const float* __restrict__ Whb)
{
    extern __shared__ float sm[];
    float* sW = sm;                     // 16 x 257
    float* sH = sm + 16 * 257;          // 256 x 64
    float* sG = sH + 256 * 64;          // 16 x 68

    int tid = threadIdx.x;
    int bid = blockIdx.x;               // 0..127
    int dir = bid & 1;
    int grp = bid >> 1;                 // 0..63
    int c0 = grp * 4;
    const float* Whh = dir ? Whb : Whf;

    for (int idx = tid; idx < 4096; idx += 256) {
        int r = idx >> 8, k = idx & 255;
        int gate = r >> 2, ci = r & 3;
        sW[r * 257 + k] = Whh[(gate * 256 + c0 + ci) * 256 + k];
    }
    g_h[dir][0][c0 + (tid >> 6)][tid & 63] = 0.f;
    float c_state = 0.f;

    int r = tid & 15, q = tid >> 4;
    int wrow = (r >> 2) * 256 + c0 + (r & 3);
    int ci2 = tid >> 6, b2 = tid & 63;

    unsigned sH_addr = (unsigned)__cvta_generic_to_shared(sH);
    const float* wrowp = &sW[r * 257];
    const float4* hq = (const float4*)sH + q;

    __syncthreads();
    if (tid == 0) { __threadfence(); g_flag[bid][0] = 1u; }

    for (int s = 0; s < TT; s++) {
        int t = dir ? (TT - 1 - s) : s;

        float4 a = __ldg((const float4*)&g_xp[dir][t][wrow][0] + q);

        if (tid < 128) {
            unsigned tgt = (unsigned)(s + 1);
            while (g_flag[tid][0] < tgt) { }
            __threadfence();
        }
        __syncthreads();

        const float4* hsrc = (const float4*)&g_h[dir][s & 1][0][0];
#pragma unroll
        for (int i = 0; i < 8; i++)
            cp_async16(sH_addr + (unsigned)((i * 256 + tid) * 16), hsrc + i * 256 + tid);
        cp_commit();
#pragma unroll
        for (int i = 8; i < 16; i++)
            cp_async16(sH_addr + (unsigned)((i * 256 + tid) * 16), hsrc + i * 256 + tid);
        cp_commit();

        float acc0 = a.x, acc1 = a.y, acc2 = a.z, acc3 = a.w;

        cp_wait<1>();
        __syncthreads();
#pragma unroll 8
        for (int k = 0; k < 128; k++) {
            float w = wrowp[k];
            float4 h4 = hq[k * 16];
            acc0 += w * h4.x; acc1 += w * h4.y;
            acc2 += w * h4.z; acc3 += w * h4.w;
        }
        cp_wait<0>();
        __syncthreads();
#pragma unroll 8
        for (int k = 128; k < 256; k++) {
            float w = wrowp[k];
            float4 h4 = hq[k * 16];
            acc0 += w * h4.x; acc1 += w * h4.y;
            acc2 += w * h4.z; acc3 += w * h4.w;
        }
        *(float4*)&sG[r * 68 + q * 4] = make_float4(acc0, acc1, acc2, acc3);
        __syncthreads();

        float gi = sG[(0 + ci2) * 68 + b2];
        float gf = sG[(4 + ci2) * 68 + b2];
        float gg = sG[(8 + ci2) * 68 + b2];
        float go = sG[(12 + ci2) * 68 + b2];
        float i_s = 1.f / (1.f + __expf(-gi));
        float f_s = 1.f / (1.f + __expf(-gf));
        float o_s = 1.f / (1.f + __expf(-go));
        float c_new = f_s * c_state + i_s * tanhf(gg);
        c_state = c_new;
        float h_new = o_s * tanhf(c_new);

        g_h[dir][(s + 1) & 1][c0 + ci2][b2] = h_new;
        g_hs[t][dir * 256 + c0 + ci2][b2] = h_new;

        __syncthreads();
        if (tid == 0) { __threadfence(); g_flag[bid][0] = (unsigned)(s + 2); }
    }

    grid_barrier(128u);
    if (tid == 0) g_flag[bid][0] = 0u;
}

// =======================================================================
// Kernel C: fc1 + ReLU + classifier -> unary. 256 blocks (one t each).
// =======================================================================
__global__ void fc_kernel(const float* __restrict__ fc1W,
                          const float* __restrict__ fc1b,
                          const float* __restrict__ clsW,
                          const float* __restrict__ clsb)
{
    extern __shared__ float sm[];
    float* sA = sm;                  // 32 x 64
    float* sB = sm + 2048;           // 32 x 128
    float* sI = sm + 6144;           // 64 x 128

    int tid = threadIdx.x;
    int t = blockIdx.x;

    int tr = tid >> 4, tn = tid & 15;
    int r0 = tr * 4, n0 = tn * 8;

    float acc[4][8];
#pragma unroll
    for (int i = 0; i < 4; i++)
#pragma unroll
        for (int j = 0; j < 8; j++) acc[i][j] = 0.f;

    for (int kc = 0; kc < 512; kc += 32) {
        __syncthreads();
        for (int idx = tid; idx < 512; idx += 256) {
            int k = idx >> 4, b4 = idx & 15;
            *(float4*)&sA[k * 64 + b4 * 4] =
                *(const float4*)&g_hs[t][kc + k][b4 * 4];
        }
        for (int idx = tid; idx < 1024; idx += 256) {
            int n = idx >> 3, kq = idx & 7;
            float4 v = *(const float4*)&fc1W[n * 512 + kc + kq * 4];
            sB[(kq * 4 + 0) * 128 + n] = v.x;
            sB[(kq * 4 + 1) * 128 + n] = v.y;
            sB[(kq * 4 + 2) * 128 + n] = v.z;
            sB[(kq * 4 + 3) * 128 + n] = v.w;
        }
        __syncthreads();
#pragma unroll
        for (int k = 0; k < 32; k++) {
            float4 a4 = *(const float4*)&sA[k * 64 + r0];
            float4 bA = *(const float4*)&sB[k * 128 + n0];
            float4 bBv = *(const float4*)&sB[k * 128 + n0 + 4];
            float av[4] = {a4.x, a4.y, a4.z, a4.w};
            float bv[8] = {bA.x, bA.y, bA.z, bA.w, bBv.x, bBv.y, bBv.z, bBv.w};
#pragma unroll
            for (int i = 0; i < 4; i++)
#pragma unroll
                for (int j = 0; j < 8; j++) acc[i][j] += av[i] * bv[j];
        }
    }

#pragma unroll
    for (int i = 0; i < 4; i++)
#pragma unroll
        for (int j = 0; j < 8; j++) {
            float v = acc[i][j] + fc1b[n0 + j];
            sI[(r0 + i) * 128 + n0 + j] = fmaxf(v, 0.f);
        }
    __syncthreads();

    float* sCW = sA;
    for (int idx = tid; idx < NL * 128; idx += 256) {
        int l = idx >> 7, k = idx & 127;
        sCW[l * 129 + k] = clsW[idx];
    }
    __syncthreads();

    for (int oi = tid; oi < 64 * NL; oi += 256) {
        int b = oi / NL, l = oi % NL;
        const float* ip = &sI[b * 128];
        const float* wp = &sCW[l * 129];
        float s = 0.f;
#pragma unroll 8
        for (int k = 0; k < 128; k++) s += ip[k] * wp[k];
        g_unary[b][t][l] = s + clsb[l];
    }
}

// =======================================================================
// Kernel D: Viterbi decode. 16 blocks x 128 threads, 1 warp per batch.
// Branchless: FMNMX max-tree + equality-mask + ffs argmax (ties -> lowest
// index, matching jnp.argmax).
// =======================================================================
__global__ void viterbi_kernel(const float* __restrict__ trans,
                               float* __restrict__ out)
{
    __shared__ float tpn_s[TL][20];                  // [prev][next], padded
    __shared__ unsigned char bps[4][TT][20];

    int tid = threadIdx.x;
    int warp = tid >> 5, lane = tid & 31;
    int b = blockIdx.x * 4 + warp;

    for (int i = tid; i < TL * TL; i += 128) {
        int p = i / TL, n = i % TL;
        tpn_s[p][n] = trans[n * TL + p];
    }
    __syncthreads();

    float tp[TL];
#pragma unroll
    for (int p = 0; p < TL; p++)
        tp[p] = (lane < TL) ? tpn_s[p][lane] : LOW_POT;

    float score = (lane == START_IDX) ? 0.f : LOW_POT;
    float u = (lane < NL) ? __ldg(&g_unary[b][0][lane]) : LOW_POT;

    for (int t = 0; t < TT; t++) {
        float u_next = (t + 1 < TT && lane < NL) ? __ldg(&g_unary[b][t + 1][lane]) : LOW_POT;

        float v[TL];
#pragma unroll
        for (int p = 0; p < TL; p++)
            v[p] = __shfl_sync(0xffffffffu, score, p) + tp[p];

        // branchless max: pairwise tree (FMNMX, no predicates)
        float w0 = fmaxf(v[0], v[1]),   w1 = fmaxf(v[2], v[3]);
        float w2 = fmaxf(v[4], v[5]),   w3 = fmaxf(v[6], v[7]);
        float w4 = fmaxf(v[8], v[9]),   w5 = fmaxf(v[10], v[11]);
        float w6 = fmaxf(v[12], v[13]), w7 = fmaxf(v[14], v[15]);
        float w8 = fmaxf(v[16], v[17]), w9 = v[18];
        float x0 = fmaxf(w0, w1), x1 = fmaxf(w2, w3);
        float x2 = fmaxf(w4, w5), x3 = fmaxf(w6, w7);
        float x4 = fmaxf(w8, w9);
        float y0 = fmaxf(x0, x1), y1 = fmaxf(x2, x3);
        float m = fmaxf(fmaxf(y0, y1), x4);

        // argmax = first index equal to max
        unsigned msk = 0u;
#pragma unroll
        for (int p = 0; p < TL; p++)
            msk |= (v[p] == m) ? (1u << p) : 0u;
        int best = __ffs(msk) - 1;

        if (lane < TL) bps[warp][t][lane] = (unsigned char)best;
        score = m + u;
        u = u_next;
    }

    float fin = (lane < TL) ? score + trans[END_IDX * TL + lane] : -3.4e38f;
    int idx = lane;
#pragma unroll
    for (int off = 16; off > 0; off >>= 1) {
        float of = __shfl_down_sync(0xffffffffu, fin, off);
        int   oi = __shfl_down_sync(0xffffffffu, idx, off);
        if (of > fin || (of == fin && oi < idx)) { fin = of; idx = oi; }
    }

    if (lane == 0) {
        out[b] = fin;
        int cur = idx;
        for (int t = TT - 1; t >= 0; t--) {
            out[BB + b * TT + t] = (float)cur;
            cur = bps[warp][t][cur];
        }
    }
}

// =======================================================================
extern "C" void kernel_launch(void* const* d_in, const int* in_sizes, int n_in,
                              void* d_out, int out_size)
{
    const int*   x     = (const int*)d_in[0];
    const float* emb   = (const float*)d_in[1];
    const float* Wif   = (const float*)d_in[2];
    const float* Whf   = (const float*)d_in[3];
    const float* bf    = (const float*)d_in[4];
    const float* Wib   = (const float*)d_in[5];
    const float* Whb   = (const float*)d_in[6];
    const float* bb    = (const float*)d_in[7];
    const float* fc1W  = (const float*)d_in[8];
    const float* fc1b  = (const float*)d_in[9];
    const float* clsW  = (const float*)d_in[10];
    const float* clsb  = (const float*)d_in[11];
    const float* trans = (const float*)d_in[12];
    float* out = (float*)d_out;

    size_t smemB = (16 * 257 + 256 * 64 + 16 * 68) * sizeof(float);   // 86336 B
    size_t smemC = (2048 + 4096 + 64 * 128) * sizeof(float);          // 57344 B
    cudaFuncSetAttribute(lstm_kernel, cudaFuncAttributeMaxDynamicSharedMemorySize, (int)smemB);
    cudaFuncSetAttribute(fc_kernel,   cudaFuncAttributeMaxDynamicSharedMemorySize, (int)smemC);

    dim3 gridA(TT, 32);
    xproj_kernel<<<gridA, 256>>>(x, emb, Wif, bf, Wib, bb);
    lstm_kernel<<<128, 256, smemB>>>(Whf, Whb);
    fc_kernel<<<TT, 256, smemC>>>(fc1W, fc1b, clsW, clsb);
    viterbi_kernel<<<BB / 4, 128>>>(trans, out);
}